// round 4
// baseline (speedup 1.0000x reference)
#include <cuda_runtime.h>
#include <math_constants.h>
#include <cstdint>

// Problem shape: x = (16, 3, 512, 512) fp32  ->  48 rows of 262144 elements.
#define ROWS        48
#define HW          262144
#define RN          16
#define CHUNKS      32                 // chunks per row
#define CHUNK_ELEMS (HW / CHUNKS)      // 8192
#define TPB         256
#define V4_PER_T    (CHUNK_ELEMS / 4 / TPB)  // 8 float4 per thread
#define NBLOCKS     (ROWS * CHUNKS)    // 1536

// Scratch (no allocations allowed -> __device__ globals).
__device__ float g_pmin[NBLOCKS];
__device__ float g_pmax[NBLOCKS];

// ---------------- Pass 1: per-(row,chunk) min/max partials ----------------
// Default-cached loads: we WANT x resident in L2 for pass 3.
__global__ void __launch_bounds__(TPB) pass1_minmax(const float4* __restrict__ x) {
    const int b     = blockIdx.x;
    const int row   = b >> 5;           // /CHUNKS
    const int chunk = b & (CHUNKS - 1);
    const float4* p = x + (size_t)row * (HW / 4) + (size_t)chunk * (CHUNK_ELEMS / 4)
                        + threadIdx.x;

    // Front-batch all loads (MLP ~ 8) then reduce.
    float4 v[V4_PER_T];
#pragma unroll
    for (int k = 0; k < V4_PER_T; k++) v[k] = p[k * TPB];

    float mn = CUDART_INF_F, mx = -CUDART_INF_F;
#pragma unroll
    for (int k = 0; k < V4_PER_T; k++) {
        mn = fminf(mn, fminf(fminf(v[k].x, v[k].y), fminf(v[k].z, v[k].w)));
        mx = fmaxf(mx, fmaxf(fmaxf(v[k].x, v[k].y), fmaxf(v[k].z, v[k].w)));
    }
#pragma unroll
    for (int o = 16; o; o >>= 1) {
        mn = fminf(mn, __shfl_xor_sync(0xFFFFFFFFu, mn, o));
        mx = fmaxf(mx, __shfl_xor_sync(0xFFFFFFFFu, mx, o));
    }
    __shared__ float smn[TPB / 32], smx[TPB / 32];
    const int w = threadIdx.x >> 5;
    if ((threadIdx.x & 31) == 0) { smn[w] = mn; smx[w] = mx; }
    __syncthreads();
    if (threadIdx.x < (TPB / 32)) {
        mn = smn[threadIdx.x];
        mx = smx[threadIdx.x];
#pragma unroll
        for (int o = (TPB / 64); o; o >>= 1) {
            mn = fminf(mn, __shfl_xor_sync(0xFFu, mn, o));
            mx = fmaxf(mx, __shfl_xor_sync(0xFFu, mx, o));
        }
        if (threadIdx.x == 0) { g_pmin[b] = mn; g_pmax[b] = mx; }
    }
}

// ---------------- Pass 2 (fused into pass 3): quantize ----------------
// Each block redundantly rebuilds its row's tables from the 32 partials
// (L2-resident, deterministic rounding -> identical tables in every block).
//
// region(x) must equal searchsorted(internal, x, side='right') exactly.
// Arithmetic estimate, then correct against the *identically rounded*
// internal bounds with +-inf sentinels -> bitwise-exact region.
// s_pad has 17 floats (banks 0..16) and s_mid 16 floats -> every dynamic
// LDS hits a distinct bank or multicasts: conflict-free.
__device__ __forceinline__ float quant_one(float v, float mn, float inv,
                                           const float* __restrict__ s_pad,
                                           const float* __restrict__ s_mid) {
    float t = (v - mn) * inv;                 // ~[0,16], off by << 1 bin
    int r = __float2int_rz(t);                // F2I(NaN)=0 (degenerate-safe)
    r = min(max(r, 0), RN - 1);
    if (v <  s_pad[r])     r--;               // est was true+1
    if (v >= s_pad[r + 1]) r++;               // est was true-1
    return s_mid[r];
}

__global__ void __launch_bounds__(TPB) pass3_quant(const float4* __restrict__ x,
                                                   float4* __restrict__ out) {
    __shared__ float s_mid[RN];
    __shared__ float s_pad[RN + 1];
    __shared__ float s_mn, s_inv;

    const int b     = blockIdx.x;
    const int row   = b >> 5;
    const int chunk = b & (CHUNKS - 1);

    const size_t base = (size_t)row * (HW / 4) + (size_t)chunk * (CHUNK_ELEMS / 4)
                      + threadIdx.x;

    // Software pipeline: issue ALL data loads first (MLP ~ 8, L2 hits),
    // overlap them with the per-row table rebuild below.
    // __ldcs = last-use streaming: this is the final read of x, so let the
    // lines evict first, leaving L2 ways for not-yet-read x of later blocks.
    float4 v[V4_PER_T];
#pragma unroll
    for (int k = 0; k < V4_PER_T; k++)
        v[k] = __ldcs(&x[base + k * TPB]);

    // --- per-row setup, warp 0 only (redundant per block, L2 hits) ---
    if (threadIdx.x < 32) {
        float mn = g_pmin[row * CHUNKS + threadIdx.x];
        float mx = g_pmax[row * CHUNKS + threadIdx.x];
#pragma unroll
        for (int o = 16; o; o >>= 1) {
            mn = fminf(mn, __shfl_xor_sync(0xFFFFFFFFu, mn, o));
            mx = fmaxf(mx, __shfl_xor_sync(0xFFFFFFFFu, mx, o));
        }
        // d = mx - mn; bounds[k] = mn + d*(k/16) with the reference's exact
        // rounding (mul then add, round-to-nearest, no FMA contraction).
        const float d = __fadd_rn(mx, -mn);
        // degenerate = |mn - mx| <= 4*eps_f32 + 1e-5*|mx|
        const bool degen =
            fabsf(__fadd_rn(mn, -mx)) <=
            __fadd_rn(4.7683716e-07f, __fmul_rn(1e-5f, fabsf(mx)));

        const int k = threadIdx.x;
        if (k <= RN) {
            // b_k and b_{k+1}, both exactly rounded
            const float bk  = __fadd_rn(mn, __fmul_rn(d, (float)k * 0.0625f));
            const float bk1 = __fadd_rn(mn, __fmul_rn(d, (float)(k + 1) * 0.0625f));
            if (k < RN)
                s_mid[k] = degen ? mn : __fmul_rn(0.5f, __fadd_rn(bk, bk1));
            // padded internal bounds: [-inf, b1..b15, +inf]
            s_pad[k] = (k == 0) ? -CUDART_INF_F : (k == RN ? CUDART_INF_F : bk);
        }
        if (k == 0) {
            s_mn  = mn;
            s_inv = __fdividef(16.0f, d);  // approx ok: only feeds the estimate
        }
    }
    __syncthreads();

    const float mn  = s_mn;
    const float inv = s_inv;
#pragma unroll
    for (int k = 0; k < V4_PER_T; k++) {
        float4 q;
        q.x = quant_one(v[k].x, mn, inv, s_pad, s_mid);
        q.y = quant_one(v[k].y, mn, inv, s_pad, s_mid);
        q.z = quant_one(v[k].z, mn, inv, s_pad, s_mid);
        q.w = quant_one(v[k].w, mn, inv, s_pad, s_mid);
        // __stcs = streaming store: output is never re-read; evict-first so
        // the 50 MB of stores don't displace still-needed x lines in L2.
        __stcs(&out[base + k * TPB], q);
    }
}

extern "C" void kernel_launch(void* const* d_in, const int* in_sizes, int n_in,
                              void* d_out, int out_size) {
    const float4* x   = (const float4*)d_in[0];
    float4*       out = (float4*)d_out;
    (void)in_sizes; (void)n_in; (void)out_size;

    pass1_minmax<<<NBLOCKS, TPB>>>(x);
    pass3_quant<<<NBLOCKS, TPB>>>(x, out);
}

// round 9
// speedup vs baseline: 1.0965x; 1.0965x over previous
#include <cuda_runtime.h>
#include <math_constants.h>
#include <cstdint>

// Problem shape: x = (16, 3, 512, 512) fp32  ->  48 rows of 262144 elements.
#define ROWS        48
#define HW          262144
#define RN          16
#define TPB         256

// Pass 1 chunking (partials layout is fixed at 32 per row).
#define P1_CHUNKS      32
#define P1_CHUNK_ELEMS (HW / P1_CHUNKS)          // 8192
#define P1_V4          (P1_CHUNK_ELEMS / 4 / TPB) // 8
#define P1_BLOCKS      (ROWS * P1_CHUNKS)         // 1536

// Pass 3 chunking: half the per-thread work, double the blocks -> fewer regs,
// higher occupancy (R4 ncu: regs=51 capped occ at 43.5%, latency-bound).
#define P3_CHUNKS      64
#define P3_CHUNK_ELEMS (HW / P3_CHUNKS)          // 4096
#define P3_V4          (P3_CHUNK_ELEMS / 4 / TPB) // 4
#define P3_BLOCKS      (ROWS * P3_CHUNKS)         // 3072

// Scratch (no allocations allowed -> __device__ globals).
__device__ float g_pmin[P1_BLOCKS];
__device__ float g_pmax[P1_BLOCKS];

// ---------------- Pass 1: per-(row,chunk) min/max partials ----------------
// Default-cached loads: we WANT x resident in L2 for pass 3.
__global__ void __launch_bounds__(TPB) pass1_minmax(const float4* __restrict__ x) {
    const int b     = blockIdx.x;
    const int row   = b >> 5;           // /P1_CHUNKS
    const int chunk = b & (P1_CHUNKS - 1);
    const float4* p = x + (size_t)row * (HW / 4) + (size_t)chunk * (P1_CHUNK_ELEMS / 4)
                        + threadIdx.x;

    float4 v[P1_V4];
#pragma unroll
    for (int k = 0; k < P1_V4; k++) v[k] = p[k * TPB];

    float mn = CUDART_INF_F, mx = -CUDART_INF_F;
#pragma unroll
    for (int k = 0; k < P1_V4; k++) {
        mn = fminf(mn, fminf(fminf(v[k].x, v[k].y), fminf(v[k].z, v[k].w)));
        mx = fmaxf(mx, fmaxf(fmaxf(v[k].x, v[k].y), fmaxf(v[k].z, v[k].w)));
    }
#pragma unroll
    for (int o = 16; o; o >>= 1) {
        mn = fminf(mn, __shfl_xor_sync(0xFFFFFFFFu, mn, o));
        mx = fmaxf(mx, __shfl_xor_sync(0xFFFFFFFFu, mx, o));
    }
    __shared__ float smn[TPB / 32], smx[TPB / 32];
    const int w = threadIdx.x >> 5;
    if ((threadIdx.x & 31) == 0) { smn[w] = mn; smx[w] = mx; }
    __syncthreads();
    if (threadIdx.x < (TPB / 32)) {
        mn = smn[threadIdx.x];
        mx = smx[threadIdx.x];
#pragma unroll
        for (int o = (TPB / 64); o; o >>= 1) {
            mn = fminf(mn, __shfl_xor_sync(0xFFu, mn, o));
            mx = fmaxf(mx, __shfl_xor_sync(0xFFu, mx, o));
        }
        if (threadIdx.x == 0) { g_pmin[b] = mn; g_pmax[b] = mx; }
    }
}

// ---------------- Pass 3: quantize (per-row table rebuilt per block) ------
// region(x) must equal searchsorted(internal, x, side='right') exactly.
// Estimate r, then parallel correction against the identically-rounded
// internal bounds (with +-inf sentinels). The two corrections are mutually
// exclusive (estimate off by at most 1 bin), so both compare against the
// ORIGINAL r:  r += (v >= pad[r+1]) - (v < pad[r]).
// s_pair[r] packs {pad[r], pad[r+1]} -> ONE LDS.64 instead of two dependent
// LDS.32; per-element serial chain drops ~95cyc -> ~63cyc. float2[16] spans
// banks {2r, 2r+1}: distinct r -> distinct banks, equal r -> multicast.
__global__ void __launch_bounds__(TPB) pass3_quant(const float4* __restrict__ x,
                                                   float4* __restrict__ out) {
    __shared__ float2 s_pair[RN];      // {pad[r], pad[r+1]}, r = 0..15
    __shared__ float  s_mid[RN];
    __shared__ float  s_mn, s_inv;

    const int b     = blockIdx.x;
    const int row   = b >> 6;           // /P3_CHUNKS
    const int chunk = b & (P3_CHUNKS - 1);

    const size_t base = (size_t)row * (HW / 4) + (size_t)chunk * (P3_CHUNK_ELEMS / 4)
                      + threadIdx.x;

    // Front-batch the data loads (last-use streaming; overlap w/ table build).
    float4 v[P3_V4];
#pragma unroll
    for (int k = 0; k < P3_V4; k++)
        v[k] = __ldcs(&x[base + k * TPB]);

    // --- per-row setup, warp 0 only (redundant per block, L2 hits) ---
    if (threadIdx.x < 32) {
        float mn = __ldg(&g_pmin[row * P1_CHUNKS + threadIdx.x]);
        float mx = __ldg(&g_pmax[row * P1_CHUNKS + threadIdx.x]);
#pragma unroll
        for (int o = 16; o; o >>= 1) {
            mn = fminf(mn, __shfl_xor_sync(0xFFFFFFFFu, mn, o));
            mx = fmaxf(mx, __shfl_xor_sync(0xFFFFFFFFu, mx, o));
        }
        // Reference's exact rounding: b_k = mn + d*(k/16), mul then add, RN.
        const float d = __fadd_rn(mx, -mn);
        const bool degen =
            fabsf(__fadd_rn(mn, -mx)) <=
            __fadd_rn(4.7683716e-07f, __fmul_rn(1e-5f, fabsf(mx)));

        const int k = threadIdx.x;
        if (k < RN) {
            const float bk  = __fadd_rn(mn, __fmul_rn(d, (float)k * 0.0625f));
            const float bk1 = __fadd_rn(mn, __fmul_rn(d, (float)(k + 1) * 0.0625f));
            s_mid[k] = degen ? mn : __fmul_rn(0.5f, __fadd_rn(bk, bk1));
            s_pair[k] = make_float2(k == 0      ? -CUDART_INF_F : bk,
                                    k == RN - 1 ?  CUDART_INF_F : bk1);
        }
        if (k == 0) {
            s_mn  = mn;
            s_inv = __fdividef(16.0f, d);  // approx ok: only feeds the estimate
        }
    }
    __syncthreads();

    const float mn  = s_mn;
    const float inv = s_inv;
#pragma unroll
    for (int k = 0; k < P3_V4; k++) {
        float4 q;
#pragma unroll
        for (int e = 0; e < 4; e++) {
            const float vv = (&v[k].x)[e];
            float t = (vv - mn) * inv;
            int r = __float2int_rz(t);          // F2I(NaN)=0 (degenerate-safe)
            r = min(max(r, 0), RN - 1);
            const float2 pr = s_pair[r];        // one LDS.64, conflict-free
            r += (vv >= pr.y) - (vv < pr.x);    // mutually-exclusive fixes
            (&q.x)[e] = s_mid[r];
        }
        // Streaming store: output never re-read; keep x resident in L2.
        __stcs(&out[base + k * TPB], q);
    }
}

extern "C" void kernel_launch(void* const* d_in, const int* in_sizes, int n_in,
                              void* d_out, int out_size) {
    const float4* x   = (const float4*)d_in[0];
    float4*       out = (float4*)d_out;
    (void)in_sizes; (void)n_in; (void)out_size;

    pass1_minmax<<<P1_BLOCKS, TPB>>>(x);
    pass3_quant<<<P3_BLOCKS, TPB>>>(x, out);
}

// round 11
// speedup vs baseline: 1.1860x; 1.0816x over previous
#include <cuda_runtime.h>
#include <math_constants.h>
#include <cstdint>

// Problem shape: x = (16, 3, 512, 512) fp32  ->  48 rows of 262144 elements.
#define ROWS        48
#define HW          262144
#define RN          16
#define TPB         256

// Pass 1 chunking (partials layout is fixed at 32 per row).
#define P1_CHUNKS      32
#define P1_CHUNK_ELEMS (HW / P1_CHUNKS)          // 8192
#define P1_V4          (P1_CHUNK_ELEMS / 4 / TPB) // 8
#define P1_BLOCKS      (ROWS * P1_CHUNKS)         // 1536

// Pass 3 chunking (R9: regs=32, occ=82.7% — keep).
#define P3_CHUNKS      64
#define P3_CHUNK_ELEMS (HW / P3_CHUNKS)          // 4096
#define P3_V4          (P3_CHUNK_ELEMS / 4 / TPB) // 4
#define P3_BLOCKS      (ROWS * P3_CHUNKS)         // 3072

// Scratch (no allocations allowed -> __device__ globals).
__device__ float g_pmin[P1_BLOCKS];
__device__ float g_pmax[P1_BLOCKS];

// ---------------- Pass 1: per-(row,chunk) min/max partials ----------------
__global__ void __launch_bounds__(TPB) pass1_minmax(const float4* __restrict__ x) {
    const int b     = blockIdx.x;
    const int row   = b >> 5;
    const int chunk = b & (P1_CHUNKS - 1);
    const float4* p = x + (size_t)row * (HW / 4) + (size_t)chunk * (P1_CHUNK_ELEMS / 4)
                        + threadIdx.x;

    float4 v[P1_V4];
#pragma unroll
    for (int k = 0; k < P1_V4; k++) v[k] = p[k * TPB];

    float mn = CUDART_INF_F, mx = -CUDART_INF_F;
#pragma unroll
    for (int k = 0; k < P1_V4; k++) {
        mn = fminf(mn, fminf(fminf(v[k].x, v[k].y), fminf(v[k].z, v[k].w)));
        mx = fmaxf(mx, fmaxf(fmaxf(v[k].x, v[k].y), fmaxf(v[k].z, v[k].w)));
    }
#pragma unroll
    for (int o = 16; o; o >>= 1) {
        mn = fminf(mn, __shfl_xor_sync(0xFFFFFFFFu, mn, o));
        mx = fmaxf(mx, __shfl_xor_sync(0xFFFFFFFFu, mx, o));
    }
    __shared__ float smn[TPB / 32], smx[TPB / 32];
    const int w = threadIdx.x >> 5;
    if ((threadIdx.x & 31) == 0) { smn[w] = mn; smx[w] = mx; }
    __syncthreads();
    if (threadIdx.x < (TPB / 32)) {
        mn = smn[threadIdx.x];
        mx = smx[threadIdx.x];
#pragma unroll
        for (int o = (TPB / 64); o; o >>= 1) {
            mn = fminf(mn, __shfl_xor_sync(0xFFu, mn, o));
            mx = fmaxf(mx, __shfl_xor_sync(0xFFu, mx, o));
        }
        if (threadIdx.x == 0) { g_pmin[b] = mn; g_pmax[b] = mx; }
    }
}

// ---------------- Pass 3: quantize, LDS-free ------------------------------
// R9 ncu: L1 pipe 47.8% (top), fma 12.4% (idle), issue 49.9% despite occ
// 82.7% -> per-element LDS chains were the binder. This version computes
// everything in registers:
//  * boundaries b_k = rn(mn + rn(d * k/16)) recomputed exactly (k/16 is
//    exact in fp32) -> region logic still bitwise searchsorted-right.
//  * mid = fmaf(d, (2r+1)/32, mn): ~1ulp from reference mid (tol 1e-3).
//  * fast path: if frac(t) is >=1e-3 away from an integer, the estimated
//    region is provably exact (est error + boundary rounding ~1e-5 bins);
//    only ~0.5% of warp-quads take the exact-correction slow path.
__device__ __forceinline__ float quant_slow(float vv, float mn, float d, float inv) {
    float s  = __fadd_rn(vv, -mn);
    float t  = __fmul_rn(s, inv);
    float kf = fminf(truncf(t), 15.0f);            // NaN -> 15 (degen d=0 -> mn)
    float u    = __fmul_rn(kf, 0.0625f);           // exact
    float blo  = __fadd_rn(mn, __fmul_rn(d, u));                    // == b_r
    float bhi  = __fadd_rn(mn, __fmul_rn(d, __fadd_rn(u, 0.0625f))); // == b_{r+1}
    float um   = __fadd_rn(u, 0.03125f);           // exact
    if (vv >= bhi) um = __fadd_rn(um,  0.0625f);   // region r+1 (side='right')
    if (vv <  blo) um = __fadd_rn(um, -0.0625f);   // region r-1
    um = fminf(um, 0.96875f);                      // clamp to region 15 mid
    return __fmaf_rn(d, um, mn);
}

__global__ void __launch_bounds__(TPB) pass3_quant(const float4* __restrict__ x,
                                                   float4* __restrict__ out) {
    __shared__ float s_mn, s_d, s_inv;

    const int b     = blockIdx.x;
    const int row   = b >> 6;
    const int chunk = b & (P3_CHUNKS - 1);

    const size_t base = (size_t)row * (HW / 4) + (size_t)chunk * (P3_CHUNK_ELEMS / 4)
                      + threadIdx.x;

    // Front-batch data loads (last-use streaming; overlap with setup).
    float4 v[P3_V4];
#pragma unroll
    for (int k = 0; k < P3_V4; k++)
        v[k] = __ldcs(&x[base + k * TPB]);

    // --- per-row setup, warp 0 only (redundant per block, L2 hits) ---
    if (threadIdx.x < 32) {
        float mn = __ldg(&g_pmin[row * P1_CHUNKS + threadIdx.x]);
        float mx = __ldg(&g_pmax[row * P1_CHUNKS + threadIdx.x]);
#pragma unroll
        for (int o = 16; o; o >>= 1) {
            mn = fminf(mn, __shfl_xor_sync(0xFFFFFFFFu, mn, o));
            mx = fmaxf(mx, __shfl_xor_sync(0xFFFFFFFFu, mx, o));
        }
        if (threadIdx.x == 0) {
            float d = __fadd_rn(mx, -mn);
            const bool degen =
                fabsf(__fadd_rn(mn, -mx)) <=
                __fadd_rn(4.7683716e-07f, __fmul_rn(1e-5f, fabsf(mx)));
            if (degen) d = 0.0f;       // all outputs collapse to mn
            s_mn  = mn;
            s_d   = d;
            s_inv = __fdividef(16.0f, d);  // d=0 -> inf; handled via NaN paths
        }
    }
    __syncthreads();

    const float mn  = s_mn;
    const float d   = s_d;
    const float inv = s_inv;
    const float EPS = 1e-3f;

#pragma unroll
    for (int k = 0; k < P3_V4; k++) {
        float4 q;
        bool susp = false;
#pragma unroll
        for (int e = 0; e < 4; e++) {
            const float vv = (&v[k].x)[e];
            float s  = __fadd_rn(vv, -mn);           // >= 0 (mn is true min)
            float t  = __fmul_rn(s, inv);            // ~[0,16]
            float kf = truncf(t);                    // F2F.rz; NaN stays NaN
            float f  = __fadd_rn(t, -kf);            // frac in [0,1)
            susp |= (f < EPS) | (f > 1.0f - EPS);    // NaN -> both false
            float kc = fminf(kf, 15.0f);             // NaN -> 15
            float um = __fmaf_rn(kc, 0.0625f, 0.03125f);  // (2r+1)/32, exact
            (&q.x)[e] = __fmaf_rn(d, um, mn);
        }
        // Warp-uniform rare branch (~0.5%/quad): exact correction.
        if (__any_sync(0xFFFFFFFFu, susp)) {
#pragma unroll
            for (int e = 0; e < 4; e++)
                (&q.x)[e] = quant_slow((&v[k].x)[e], mn, d, inv);
        }
        __stcs(&out[base + k * TPB], q);             // streaming: never re-read
    }
}

extern "C" void kernel_launch(void* const* d_in, const int* in_sizes, int n_in,
                              void* d_out, int out_size) {
    const float4* x   = (const float4*)d_in[0];
    float4*       out = (float4*)d_out;
    (void)in_sizes; (void)n_in; (void)out_size;

    pass1_minmax<<<P1_BLOCKS, TPB>>>(x);
    pass3_quant<<<P3_BLOCKS, TPB>>>(x, out);
}

// round 15
// speedup vs baseline: 1.2137x; 1.0234x over previous
#include <cuda_runtime.h>
#include <math_constants.h>
#include <cstdint>

// Problem shape: x = (16, 3, 512, 512) fp32  ->  48 rows of 262144 elements.
#define ROWS        48
#define HW          262144
#define RN          16
#define TPB         256

// Pass 1 chunking (partials layout fixed at 32 per row -> one warp rebuild).
#define P1_CHUNKS      32
#define P1_CHUNK_ELEMS (HW / P1_CHUNKS)          // 8192
#define P1_V4          (P1_CHUNK_ELEMS / 4 / TPB) // 8
#define P1_BLOCKS      (ROWS * P1_CHUNKS)         // 1536

// Pass 3 chunking (R9/R11: regs 32, occ ~80% — keep shape).
#define P3_CHUNKS      64
#define P3_CHUNK_ELEMS (HW / P3_CHUNKS)          // 4096
#define P3_V4          (P3_CHUNK_ELEMS / 4 / TPB) // 4
#define P3_BLOCKS      (ROWS * P3_CHUNKS)         // 3072

// Scratch (no allocations allowed -> __device__ globals).
__device__ float g_pmin[P1_BLOCKS];
__device__ float g_pmax[P1_BLOCKS];

// ---------------- Pass 1: per-(row,chunk) min/max partials ----------------
__global__ void __launch_bounds__(TPB) pass1_minmax(const float4* __restrict__ x) {
    const int b     = blockIdx.x;
    const int row   = b >> 5;
    const int chunk = b & (P1_CHUNKS - 1);
    const float4* p = x + (size_t)row * (HW / 4) + (size_t)chunk * (P1_CHUNK_ELEMS / 4)
                        + threadIdx.x;

    float4 v[P1_V4];
#pragma unroll
    for (int k = 0; k < P1_V4; k++) v[k] = p[k * TPB];

    float mn = CUDART_INF_F, mx = -CUDART_INF_F;
#pragma unroll
    for (int k = 0; k < P1_V4; k++) {
        mn = fminf(mn, fminf(fminf(v[k].x, v[k].y), fminf(v[k].z, v[k].w)));
        mx = fmaxf(mx, fmaxf(fmaxf(v[k].x, v[k].y), fmaxf(v[k].z, v[k].w)));
    }
#pragma unroll
    for (int o = 16; o; o >>= 1) {
        mn = fminf(mn, __shfl_xor_sync(0xFFFFFFFFu, mn, o));
        mx = fmaxf(mx, __shfl_xor_sync(0xFFFFFFFFu, mx, o));
    }
    __shared__ float smn[TPB / 32], smx[TPB / 32];
    const int w = threadIdx.x >> 5;
    if ((threadIdx.x & 31) == 0) { smn[w] = mn; smx[w] = mx; }
    __syncthreads();
    if (threadIdx.x < (TPB / 32)) {
        mn = smn[threadIdx.x];
        mx = smx[threadIdx.x];
#pragma unroll
        for (int o = (TPB / 64); o; o >>= 1) {
            mn = fminf(mn, __shfl_xor_sync(0xFFu, mn, o));
            mx = fmaxf(mx, __shfl_xor_sync(0xFFu, mx, o));
        }
        if (threadIdx.x == 0) { g_pmin[b] = mn; g_pmax[b] = mx; }
    }
}

// ---------------- Pass 3: quantize — no smem, no barriers -----------------
// R11 ncu: L1 35.7%, fma 14.8%, issue 41.5% @ occ 80% -> still latency-bound;
// hypothesis: block-level coupling (warp0 setup + BAR) + exposed F2F chains.
// Fix: EVERY warp rebuilds the row params itself (32 partial loads, L2 hits,
// butterfly reduce) fully overlapped with its front-batched data loads.
// Warps are now completely independent: pure stream kernel.
//
// Region logic (verified rel_err=8.6e-8 in R11): estimate region; if frac(t)
// is >=1e-3 from an integer the estimate is provably exact (est+rounding err
// ~1e-5 bins); rare slow path recomputes the two reference-rounded bounds
// b_k = rn(mn + rn(d*k/16)) -> exact searchsorted-right region.
__device__ __forceinline__ float quant_slow(float vv, float mn, float d, float inv) {
    float s  = __fadd_rn(vv, -mn);
    float t  = __fmul_rn(s, inv);
    float kf = fminf(truncf(t), 15.0f);            // NaN -> 15 (degen d=0 -> mn)
    float u    = __fmul_rn(kf, 0.0625f);           // exact
    float blo  = __fadd_rn(mn, __fmul_rn(d, u));                    // == b_r
    float bhi  = __fadd_rn(mn, __fmul_rn(d, __fadd_rn(u, 0.0625f))); // == b_{r+1}
    float um   = __fadd_rn(u, 0.03125f);           // exact
    if (vv >= bhi) um = __fadd_rn(um,  0.0625f);   // region r+1 (side='right')
    if (vv <  blo) um = __fadd_rn(um, -0.0625f);   // region r-1
    um = fminf(um, 0.96875f);                      // clamp to region 15 mid
    return __fmaf_rn(d, um, mn);
}

__global__ void __launch_bounds__(TPB) pass3_quant(const float4* __restrict__ x,
                                                   float4* __restrict__ out) {
    const int b     = blockIdx.x;
    const int row   = b >> 6;
    const int chunk = b & (P3_CHUNKS - 1);
    const int lane  = threadIdx.x & 31;

    const size_t base = (size_t)row * (HW / 4) + (size_t)chunk * (P3_CHUNK_ELEMS / 4)
                      + threadIdx.x;

    // Front-batch data loads (last-use streaming); their latency covers the
    // per-warp setup below.
    float4 v[P3_V4];
#pragma unroll
    for (int k = 0; k < P3_V4; k++)
        v[k] = __ldcs(&x[base + k * TPB]);

    // --- per-WARP setup: each warp rebuilds row params (L2 hits, no BAR) ---
    float mn = __ldg(&g_pmin[row * P1_CHUNKS + lane]);
    float mx = __ldg(&g_pmax[row * P1_CHUNKS + lane]);
#pragma unroll
    for (int o = 16; o; o >>= 1) {
        mn = fminf(mn, __shfl_xor_sync(0xFFFFFFFFu, mn, o));
        mx = fmaxf(mx, __shfl_xor_sync(0xFFFFFFFFu, mx, o));
    }
    float d = __fadd_rn(mx, -mn);
    const bool degen =
        fabsf(__fadd_rn(mn, -mx)) <=
        __fadd_rn(4.7683716e-07f, __fmul_rn(1e-5f, fabsf(mx)));
    if (degen) d = 0.0f;                     // all outputs collapse to mn
    const float inv = __fdividef(16.0f, d);  // d=0 -> inf; NaN paths handle it

    const float HALF_BAND = 0.499f;          // 0.5 - EPS, EPS = 1e-3

#pragma unroll
    for (int k = 0; k < P3_V4; k++) {
        float4 q;
        bool susp = false;
#pragma unroll
        for (int e = 0; e < 4; e++) {
            const float vv = (&v[k].x)[e];
            float s  = __fadd_rn(vv, -mn);           // >= 0 (mn is true min)
            float t  = __fmul_rn(s, inv);            // ~[0,16]
            float kf = truncf(t);                    // F2F.rz; NaN stays NaN
            float f  = __fadd_rn(t, -kf);            // frac in [0,1)
            susp |= fabsf(__fadd_rn(f, -0.5f)) > HALF_BAND;  // NaN -> false
            float kc = fminf(kf, 15.0f);             // NaN -> 15
            float um = __fmaf_rn(kc, 0.0625f, 0.03125f);  // (2r+1)/32, exact
            (&q.x)[e] = __fmaf_rn(d, um, mn);
        }
        // Warp-uniform rare branch (~0.5%/quad): exact correction.
        if (__any_sync(0xFFFFFFFFu, susp)) {
#pragma unroll
            for (int e = 0; e < 4; e++)
                (&q.x)[e] = quant_slow((&v[k].x)[e], mn, d, inv);
        }
        __stcs(&out[base + k * TPB], q);             // streaming: never re-read
    }
}

extern "C" void kernel_launch(void* const* d_in, const int* in_sizes, int n_in,
                              void* d_out, int out_size) {
    const float4* x   = (const float4*)d_in[0];
    float4*       out = (float4*)d_out;
    (void)in_sizes; (void)n_in; (void)out_size;

    pass1_minmax<<<P1_BLOCKS, TPB>>>(x);
    pass3_quant<<<P3_BLOCKS, TPB>>>(x, out);
}